// round 1
// baseline (speedup 1.0000x reference)
#include <cuda_runtime.h>

// ----------------------------------------------------------------------------
// PhaseLinear: out[b,o] = sum_c coef[b,c] * ( x[b,:] . W[c,o,:] + bias[c,o] )
// coef from Catmull-Rom basis with the reference's tt=[1,t^2,t^3,0] quirk:
//   c0 = t^3 - 0.5 t^2 ; c1 = 1 - 2.5 t^3 ; c2 = 0.5 t^2 + 2 t^3 ; c3 = -0.5 t^3
//   t  = phase/(1.5pi) if phase < 1.5pi else (phase - 0.5pi)/(1.5pi)
//
// Stage 1: coef kernel (1024 rows)
// Stage 2: 4x NT-GEMM (split over blockIdx.z = control point c), partials to
//          a __device__ scratch buffer. 128x128x16 tiles, 8x8 microtile,
//          packed fma.rn.f32x2 accumulation (2 MACs/lane/instr).
// Stage 3: reduce kernel: out = sum_c coef[b,c]*(partial_c + bias_c)
// ----------------------------------------------------------------------------

#define BATCH 1024
#define INF   512
#define OUTF  512
#define NCP   4

__device__ float  g_partial[NCP * BATCH * OUTF];   // 8 MB scratch (allowed: static __device__)
__device__ float4 g_coef[BATCH];

// ---- packed f32x2 helpers ---------------------------------------------------
__device__ __forceinline__ unsigned long long pack2(float lo, float hi) {
    unsigned long long r;
    asm("mov.b64 %0, {%1, %2};"
        : "=l"(r) : "r"(__float_as_uint(lo)), "r"(__float_as_uint(hi)));
    return r;
}
__device__ __forceinline__ void fma2(unsigned long long& d,
                                     unsigned long long a,
                                     unsigned long long b) {
    asm("fma.rn.f32x2 %0, %1, %2, %3;" : "=l"(d) : "l"(a), "l"(b), "l"(d));
}

// ---- Stage 1: spline coefficients -------------------------------------------
__global__ void coef_kernel(const float* __restrict__ phase) {
    int b = blockIdx.x * blockDim.x + threadIdx.x;
    if (b >= BATCH) return;
    const float PI = 3.14159265358979323846f;
    float p = phase[b];
    float t = (p < 1.5f * PI) ? (p / (1.5f * PI)) : ((p - 0.5f * PI) / (1.5f * PI));
    float t2 = t * t;
    float t3 = t2 * t;
    float4 c;
    c.x = t3 - 0.5f * t2;
    c.y = 1.0f - 2.5f * t3;
    c.z = 0.5f * t2 + 2.0f * t3;
    c.w = -0.5f * t3;
    g_coef[b] = c;
}

// ---- Stage 2: NT GEMM, one control point per blockIdx.z ---------------------
// A = input [1024 x 512] row-major (K contiguous)
// B = weights[c]  [512 x 512] row-major [o][i] (K contiguous)  -> NT GEMM
// P[c][b][o] = sum_i A[b,i] * B[o,i]
__global__ void __launch_bounds__(256, 1)
gemm_kernel(const float* __restrict__ X, const float* __restrict__ W) {
    __shared__ float As[16][128];
    __shared__ float Bs[16][128];

    const int c = blockIdx.z;
    const float* A = X + blockIdx.x * 128 * INF;
    const float* B = W + c * (OUTF * INF) + blockIdx.y * 128 * INF;
    float* P = g_partial + c * (BATCH * OUTF)
             + blockIdx.x * 128 * OUTF + blockIdx.y * 128;

    const int tid  = threadIdx.x;
    const int lrow = tid & 127;   // which m-row / n-row of the tile this thread loads
    const int kq   = tid >> 7;    // 0 or 1: which pair of k-quads
    const int tx   = tid & 15;    // n position of microtile
    const int ty   = tid >> 4;    // m position of microtile

    unsigned long long acc[8][4];
    #pragma unroll
    for (int mi = 0; mi < 8; mi++)
        #pragma unroll
        for (int nj = 0; nj < 4; nj++)
            acc[mi][nj] = 0ULL;   // bit pattern of (0.f, 0.f)

    for (int kt = 0; kt < INF; kt += 16) {
        // load 16x128 tiles of A and B (k-major in shared, conflict-free stores)
        #pragma unroll
        for (int L = 0; L < 2; L++) {
            const int kk0 = (kq * 2 + L) * 4;   // 0,4,8,12
            float4 av = *(const float4*)(A + lrow * INF + kt + kk0);
            As[kk0 + 0][lrow] = av.x;
            As[kk0 + 1][lrow] = av.y;
            As[kk0 + 2][lrow] = av.z;
            As[kk0 + 3][lrow] = av.w;
            float4 bv = *(const float4*)(B + lrow * INF + kt + kk0);
            Bs[kk0 + 0][lrow] = bv.x;
            Bs[kk0 + 1][lrow] = bv.y;
            Bs[kk0 + 2][lrow] = bv.z;
            Bs[kk0 + 3][lrow] = bv.w;
        }
        __syncthreads();

        #pragma unroll
        for (int kk = 0; kk < 16; kk++) {
            float4 a0 = *(const float4*)&As[kk][ty * 8];
            float4 a1 = *(const float4*)&As[kk][ty * 8 + 4];
            float4 b0 = *(const float4*)&Bs[kk][tx * 8];
            float4 b1 = *(const float4*)&Bs[kk][tx * 8 + 4];

            unsigned long long bp[4];
            bp[0] = pack2(b0.x, b0.y);
            bp[1] = pack2(b0.z, b0.w);
            bp[2] = pack2(b1.x, b1.y);
            bp[3] = pack2(b1.z, b1.w);

            float am[8] = {a0.x, a0.y, a0.z, a0.w, a1.x, a1.y, a1.z, a1.w};
            #pragma unroll
            for (int mi = 0; mi < 8; mi++) {
                unsigned long long ap = pack2(am[mi], am[mi]);
                #pragma unroll
                for (int nj = 0; nj < 4; nj++)
                    fma2(acc[mi][nj], ap, bp[nj]);
            }
        }
        __syncthreads();
    }

    // epilogue: packed (lo,hi) is little-endian (n, n+1) -> direct 8B stores
    #pragma unroll
    for (int mi = 0; mi < 8; mi++) {
        float* rowp = P + (ty * 8 + mi) * OUTF + tx * 8;
        #pragma unroll
        for (int nj = 0; nj < 4; nj++)
            *(unsigned long long*)(rowp + nj * 2) = acc[mi][nj];
    }
}

// ---- Stage 3: blend partials with coefficients + bias ------------------------
__global__ void reduce_kernel(const float* __restrict__ biases,
                              float* __restrict__ out) {
    int idx = blockIdx.x * blockDim.x + threadIdx.x;  // float4 index, 0..131071
    int b  = idx >> 7;       // OUTF/4 = 128 float4 per row
    int o4 = idx & 127;

    float4 cf = g_coef[b];
    float cc[4] = {cf.x, cf.y, cf.z, cf.w};

    const float4* P4 = (const float4*)g_partial;
    const float4* B4 = (const float4*)biases;

    float4 r = make_float4(0.f, 0.f, 0.f, 0.f);
    #pragma unroll
    for (int c = 0; c < NCP; c++) {
        float4 p  = P4[c * (BATCH * OUTF / 4) + b * 128 + o4];
        float4 bb = B4[c * (OUTF / 4) + o4];
        r.x = fmaf(cc[c], p.x + bb.x, r.x);
        r.y = fmaf(cc[c], p.y + bb.y, r.y);
        r.z = fmaf(cc[c], p.z + bb.z, r.z);
        r.w = fmaf(cc[c], p.w + bb.w, r.w);
    }
    ((float4*)out)[idx] = r;
}

// ---- launch ------------------------------------------------------------------
extern "C" void kernel_launch(void* const* d_in, const int* in_sizes, int n_in,
                              void* d_out, int out_size) {
    const float* input   = (const float*)d_in[0];   // [1024,512]
    const float* phase   = (const float*)d_in[1];   // [1024]
    const float* weights = (const float*)d_in[2];   // [4,512,512]
    const float* biases  = (const float*)d_in[3];   // [4,512]
    float* out = (float*)d_out;                     // [1024,512]

    coef_kernel<<<4, 256>>>(phase);

    dim3 ggrid(BATCH / 128, OUTF / 128, NCP);       // (8,4,4) = 128 CTAs
    gemm_kernel<<<ggrid, 256>>>(input, weights);

    reduce_kernel<<<(BATCH * OUTF / 4) / 256, 256>>>(biases, out);
}

// round 6
// speedup vs baseline: 1.6315x; 1.6315x over previous
#include <cuda_runtime.h>
#include <cuda_bf16.h>
#include <cstdint>

// ----------------------------------------------------------------------------
// PhaseLinear, single fused kernel via mma.sync m16n8k16 bf16 (HMMA), hi/lo
// split compensation:  x = hi + lo (bf16);  x*w ~= hi*wh + hi*wl + lo*wh.
//   out[b,o] = sum_c coef[b,c] * ( x[b,:] . W[c,o,:] + bias[c,o] )
// Grid (16,8) = 128 CTAs, 64x64 tiles, 256 threads (8 warps, 2x4, 32x16 each).
// ----------------------------------------------------------------------------

#define BATCH 1024
#define INF   512
#define OUTF  512
#define NCP   4

#define BM 64
#define BN 64
#define BK 64
#define LDW 36            // row stride in 4B words (72 bf16 = 144B, pad for banks)

__device__ __forceinline__ void split2(float x, float y, uint32_t& h, uint32_t& l) {
    __nv_bfloat16 hx = __float2bfloat16(x);
    __nv_bfloat16 hy = __float2bfloat16(y);
    float rx = x - __bfloat162float(hx);
    float ry = y - __bfloat162float(hy);
    __nv_bfloat16 lx = __float2bfloat16(rx);
    __nv_bfloat16 ly = __float2bfloat16(ry);
    h = ((uint32_t)__bfloat16_as_ushort(hy) << 16) | __bfloat16_as_ushort(hx);
    l = ((uint32_t)__bfloat16_as_ushort(ly) << 16) | __bfloat16_as_ushort(lx);
}

__device__ __forceinline__ void mma16816(float* d, const uint32_t* a, const uint32_t* b) {
    asm volatile(
        "mma.sync.aligned.m16n8k16.row.col.f32.bf16.bf16.f32 "
        "{%0,%1,%2,%3}, {%4,%5,%6,%7}, {%8,%9}, {%0,%1,%2,%3};"
        : "+f"(d[0]), "+f"(d[1]), "+f"(d[2]), "+f"(d[3])
        : "r"(a[0]), "r"(a[1]), "r"(a[2]), "r"(a[3]), "r"(b[0]), "r"(b[1]));
}

__global__ void __launch_bounds__(256)
fused_kernel(const float* __restrict__ X, const float* __restrict__ phase,
             const float* __restrict__ W, const float* __restrict__ biases,
             float* __restrict__ out) {
    // SMEM tiles as 4B words: [64 rows][36 words]; bf16 pair (k, k+1) per word.
    __shared__ uint32_t Ah[BM * LDW], Al[BM * LDW];
    __shared__ uint32_t Bh[BN * LDW], Bl[BN * LDW];
    __shared__ float coef_s[NCP][BM];
    __shared__ float bias_s[NCP][BN];

    const int tid  = threadIdx.x;
    const int wid  = tid >> 5;
    const int lane = tid & 31;
    const int g    = lane >> 2;     // fragment group row 0..7
    const int t    = lane & 3;      // fragment thread-in-group 0..3
    const int wm   = wid & 1;       // warp m-half (0..1)
    const int wn   = wid >> 1;      // warp n-quarter (0..3)
    const int mx   = blockIdx.x;    // 0..15  batch tile
    const int ny   = blockIdx.y;    // 0..7   out-col tile

    // ---- per-CTA coef + bias tables ----
    if (tid < BM) {
        const float PI = 3.14159265358979323846f;
        float p = phase[mx * BM + tid];
        float tt = (p < 1.5f * PI) ? (p / (1.5f * PI)) : ((p - 0.5f * PI) / (1.5f * PI));
        float t2 = tt * tt, t3 = t2 * tt;
        coef_s[0][tid] = t3 - 0.5f * t2;
        coef_s[1][tid] = 1.0f - 2.5f * t3;
        coef_s[2][tid] = 0.5f * t2 + 2.0f * t3;
        coef_s[3][tid] = -0.5f * t3;
    } else if (tid < 128) {
        int j = tid - 64;
        #pragma unroll
        for (int c = 0; c < NCP; c++)
            bias_s[c][j] = biases[c * OUTF + ny * BN + j];
    }

    float accF[2][2][4];
    #pragma unroll
    for (int i = 0; i < 2; i++)
        #pragma unroll
        for (int j = 0; j < 2; j++)
            #pragma unroll
            for (int r = 0; r < 4; r++) accF[i][j][r] = 0.f;

    const float* Abase = X + (size_t)mx * BM * INF;

    for (int c = 0; c < NCP; c++) {
        const float* Wc = W + (size_t)c * OUTF * INF + (size_t)ny * BN * INF;

        float acc[2][2][4];
        #pragma unroll
        for (int i = 0; i < 2; i++)
            #pragma unroll
            for (int j = 0; j < 2; j++)
                #pragma unroll
                for (int r = 0; r < 4; r++) acc[i][j][r] = 0.f;

        for (int kc = 0; kc < INF / BK; kc++) {
            __syncthreads();   // previous compute done before overwrite
            // fill: 1024 float4 per matrix, 256 threads -> 4 each
            #pragma unroll
            for (int i = 0; i < 4; i++) {
                int u   = i * 256 + tid;      // 0..1023
                int row = u >> 4;             // 0..63
                int fi  = u & 15;             // float4 within 64-float row
                int w0  = row * LDW + fi * 2; // word slot (fi*4 bf16 = 2 words)

                float4 va = *(const float4*)(Abase + (size_t)row * INF + kc * BK + fi * 4);
                uint32_t h0, l0, h1, l1;
                split2(va.x, va.y, h0, l0);
                split2(va.z, va.w, h1, l1);
                Ah[w0] = h0; Ah[w0 + 1] = h1;
                Al[w0] = l0; Al[w0 + 1] = l1;

                float4 vb = *(const float4*)(Wc + (size_t)row * INF + kc * BK + fi * 4);
                split2(vb.x, vb.y, h0, l0);
                split2(vb.z, vb.w, h1, l1);
                Bh[w0] = h0; Bh[w0 + 1] = h1;
                Bl[w0] = l0; Bl[w0 + 1] = l1;
            }
            __syncthreads();

            #pragma unroll
            for (int ks = 0; ks < 4; ks++) {     // 4 x k16 steps
                const int koff = ks * 8 + t;     // word offset within row

                uint32_t ah[2][4], al[2][4];
                #pragma unroll
                for (int tm = 0; tm < 2; tm++) {
                    int r0 = (wm * 32 + tm * 16 + g) * LDW;
                    int r8 = r0 + 8 * LDW;
                    ah[tm][0] = Ah[r0 + koff];     ah[tm][1] = Ah[r8 + koff];
                    ah[tm][2] = Ah[r0 + koff + 4]; ah[tm][3] = Ah[r8 + koff + 4];
                    al[tm][0] = Al[r0 + koff];     al[tm][1] = Al[r8 + koff];
                    al[tm][2] = Al[r0 + koff + 4]; al[tm][3] = Al[r8 + koff + 4];
                }
                uint32_t bh[2][2], bl[2][2];
                #pragma unroll
                for (int tn = 0; tn < 2; tn++) {
                    int nb = (wn * 16 + tn * 8 + g) * LDW;
                    bh[tn][0] = Bh[nb + koff]; bh[tn][1] = Bh[nb + koff + 4];
                    bl[tn][0] = Bl[nb + koff]; bl[tn][1] = Bl[nb + koff + 4];
                }
                #pragma unroll
                for (int tm = 0; tm < 2; tm++)
                    #pragma unroll
                    for (int tn = 0; tn < 2; tn++) {
                        mma16816(acc[tm][tn], ah[tm], bh[tn]);
                        mma16816(acc[tm][tn], ah[tm], bl[tn]);
                        mma16816(acc[tm][tn], al[tm], bh[tn]);
                    }
            }
        }

        // blend this control point into the final accumulator
        #pragma unroll
        for (int tm = 0; tm < 2; tm++) {
            float ccg  = coef_s[c][wm * 32 + tm * 16 + g];
            float ccg8 = coef_s[c][wm * 32 + tm * 16 + g + 8];
            #pragma unroll
            for (int tn = 0; tn < 2; tn++) {
                float b0 = bias_s[c][wn * 16 + tn * 8 + 2 * t];
                float b1 = bias_s[c][wn * 16 + tn * 8 + 2 * t + 1];
                accF[tm][tn][0] = fmaf(ccg,  acc[tm][tn][0] + b0, accF[tm][tn][0]);
                accF[tm][tn][1] = fmaf(ccg,  acc[tm][tn][1] + b1, accF[tm][tn][1]);
                accF[tm][tn][2] = fmaf(ccg8, acc[tm][tn][2] + b0, accF[tm][tn][2]);
                accF[tm][tn][3] = fmaf(ccg8, acc[tm][tn][3] + b1, accF[tm][tn][3]);
            }
        }
    }

    // ---- store 64x64 tile ----
    #pragma unroll
    for (int tm = 0; tm < 2; tm++) {
        int row0 = mx * BM + wm * 32 + tm * 16 + g;
        #pragma unroll
        for (int tn = 0; tn < 2; tn++) {
            int col = ny * BN + wn * 16 + tn * 8 + 2 * t;
            float2 lo = make_float2(accF[tm][tn][0], accF[tm][tn][1]);
            float2 hi = make_float2(accF[tm][tn][2], accF[tm][tn][3]);
            *(float2*)(out + (size_t)row0 * OUTF + col)       = lo;
            *(float2*)(out + (size_t)(row0 + 8) * OUTF + col) = hi;
        }
    }
}

// ---------------- launch -------------------------------------------------------
extern "C" void kernel_launch(void* const* d_in, const int* in_sizes, int n_in,
                              void* d_out, int out_size) {
    const float* input   = (const float*)d_in[0];   // [1024,512]
    const float* phase   = (const float*)d_in[1];   // [1024]
    const float* weights = (const float*)d_in[2];   // [4,512,512]
    const float* biases  = (const float*)d_in[3];   // [4,512]
    float* out = (float*)d_out;                     // [1024,512]

    dim3 grid(BATCH / BM, OUTF / BN);               // (16,8) = 128 CTAs
    fused_kernel<<<grid, 256>>>(input, phase, weights, biases, out);
}

// round 7
// speedup vs baseline: 2.4244x; 1.4860x over previous
#include <cuda_runtime.h>
#include <cuda_bf16.h>
#include <cstdint>

// ----------------------------------------------------------------------------
// PhaseLinear, 3 kernels:
//  1) convert: fp32 X,W -> bf16 hi/lo planes in __device__ scratch
//  2) gemm: y4[c][b][o] = X.W[c]^T via mma.sync bf16, 3-term hi/lo compensation
//     128x128 CTA tiles over concat-N=2048, cp.async 3-stage pipeline, ldmatrix
//  3) reduce: out = sum_c coef[b,c]*(y4 + bias)
// ----------------------------------------------------------------------------

#define BATCH 1024
#define INF   512
#define OUTF  512
#define NCP   4
#define NCAT  (NCP * OUTF)          // 2048

__device__ float g_y4[NCP * BATCH * OUTF];                  // 8 MB
__device__ __nv_bfloat16 g_Xh[BATCH * INF], g_Xl[BATCH * INF];   // 1 MB each
__device__ __nv_bfloat16 g_Wh[NCAT * INF],  g_Wl[NCAT * INF];    // 2 MB each

// ---------------- helpers ----------------------------------------------------
__device__ __forceinline__ uint32_t smem_u32(const void* p) {
    uint32_t a;
    asm("{ .reg .u64 t; cvta.to.shared.u64 t, %1; cvt.u32.u64 %0, t; }"
        : "=r"(a) : "l"(p));
    return a;
}
__device__ __forceinline__ void split_pair(float x, float y, uint32_t& h, uint32_t& l) {
    asm("cvt.rn.bf16x2.f32 %0, %1, %2;" : "=r"(h) : "f"(y), "f"(x));  // {hi=y, lo=x}
    float hx = __uint_as_float(h << 16);
    float hy = __uint_as_float(h & 0xFFFF0000u);
    float rx = x - hx, ry = y - hy;
    asm("cvt.rn.bf16x2.f32 %0, %1, %2;" : "=r"(l) : "f"(ry), "f"(rx));
}
__device__ __forceinline__ void mma16816(float* d, const uint32_t* a, const uint32_t* b) {
    asm volatile(
        "mma.sync.aligned.m16n8k16.row.col.f32.bf16.bf16.f32 "
        "{%0,%1,%2,%3}, {%4,%5,%6,%7}, {%8,%9}, {%0,%1,%2,%3};"
        : "+f"(d[0]), "+f"(d[1]), "+f"(d[2]), "+f"(d[3])
        : "r"(a[0]), "r"(a[1]), "r"(a[2]), "r"(a[3]), "r"(b[0]), "r"(b[1]));
}
__device__ __forceinline__ void ldsm4(uint32_t* r, uint32_t addr) {
    asm volatile("ldmatrix.sync.aligned.m8n8.x4.shared.b16 {%0,%1,%2,%3}, [%4];"
        : "=r"(r[0]), "=r"(r[1]), "=r"(r[2]), "=r"(r[3]) : "r"(addr));
}
__device__ __forceinline__ void cpasync16(uint32_t dst, const void* src) {
    asm volatile("cp.async.cg.shared.global [%0], [%1], 16;" :: "r"(dst), "l"(src));
}

// ---------------- 1) convert --------------------------------------------------
__global__ void convert_kernel(const float* __restrict__ X, const float* __restrict__ W) {
    int i = blockIdx.x * blockDim.x + threadIdx.x;     // float4 index
    const int NX = BATCH * INF / 4;                    // 131072
    const int NW = NCAT * INF / 4;                     // 262144
    float4 v; uint2* dh; uint2* dl;
    if (i < NX) {
        v = ((const float4*)X)[i];
        dh = (uint2*)g_Xh + i; dl = (uint2*)g_Xl + i;
    } else {
        int j = i - NX;
        if (j >= NW) return;
        v = ((const float4*)W)[j];
        dh = (uint2*)g_Wh + j; dl = (uint2*)g_Wl + j;
    }
    uint2 hp, lp;
    split_pair(v.x, v.y, hp.x, lp.x);
    split_pair(v.z, v.w, hp.y, lp.y);
    *dh = hp; *dl = lp;
}

// ---------------- 2) GEMM -----------------------------------------------------
// Tiles: CTA 128(m) x 128(n-concat), BK=32. SMEM stage = Ah,Al,Bh,Bl each
// 128 rows x 80B (64B data + 16B pad) = 10240B -> 40960B/stage, 3 stages.
#define ROWB   80
#define TILE_B 10240
#define STAGE_B 40960
#define NSTAGE 3
#define NCHUNK (INF / 32)     // 16
#define SMEM_DYN (NSTAGE * STAGE_B)

__global__ void __launch_bounds__(256, 1)
gemm_kernel(int dummy) {
    extern __shared__ __align__(128) char smem[];
    const uint32_t sbase = smem_u32(smem);

    const int tid  = threadIdx.x;
    const int wid  = tid >> 5;
    const int lane = tid & 31;
    const int g    = lane >> 2;
    const int t    = lane & 3;
    const int wm   = wid & 1;      // 0..1 -> m offset wm*64
    const int wn   = wid >> 1;     // 0..3 -> n offset wn*32
    const int mx   = blockIdx.x;   // 0..7
    const int ny   = blockIdx.y;   // 0..15 over concat N

    // ldmatrix lane-address components (byte offsets)
    const uint32_t a_lane = ((((lane >> 3) & 1) * 8 + (lane & 7)) * ROWB)
                          + ((lane >> 4) * 8) * 2;
    const uint32_t b_lane = ((((lane >> 4) & 1) * 8 + (lane & 7)) * ROWB)
                          + (((lane >> 3) & 1) * 8) * 2;

    // global row bases
    const __nv_bfloat16* xh = g_Xh + (size_t)(mx * 128) * INF;
    const __nv_bfloat16* xl = g_Xl + (size_t)(mx * 128) * INF;
    const __nv_bfloat16* wh = g_Wh + (size_t)(ny * 128) * INF;
    const __nv_bfloat16* wl = g_Wl + (size_t)(ny * 128) * INF;

    // fill one stage for K-chunk kc
    auto fill = [&](int stage, int kc) {
        #pragma unroll
        for (int i = 0; i < 8; i++) {
            int u    = i * 256 + tid;        // 0..2047
            int tile = u >> 9;               // 0 Ah,1 Al,2 Bh,3 Bl
            int r    = (u >> 2) & 127;
            int seg  = u & 3;
            const __nv_bfloat16* src;
            if      (tile == 0) src = xh + (size_t)r * INF + kc * 32 + seg * 8;
            else if (tile == 1) src = xl + (size_t)r * INF + kc * 32 + seg * 8;
            else if (tile == 2) src = wh + (size_t)r * INF + kc * 32 + seg * 8;
            else                src = wl + (size_t)r * INF + kc * 32 + seg * 8;
            uint32_t dst = sbase + stage * STAGE_B + tile * TILE_B + r * ROWB + seg * 16;
            cpasync16(dst, src);
        }
        asm volatile("cp.async.commit_group;" ::: "memory");
    };

    float acc[4][4][4];
    #pragma unroll
    for (int mf = 0; mf < 4; mf++)
        #pragma unroll
        for (int nf = 0; nf < 4; nf++)
            #pragma unroll
            for (int r = 0; r < 4; r++) acc[mf][nf][r] = 0.f;

    fill(0, 0); fill(1, 1); fill(2, 2);

    for (int kc = 0; kc < NCHUNK; kc++) {
        if (kc <= NCHUNK - 4)
            asm volatile("cp.async.wait_group 2;" ::: "memory");
        else
            asm volatile("cp.async.wait_group 0;" ::: "memory");
        __syncthreads();

        const int st = kc % NSTAGE;
        const uint32_t sA = sbase + st * STAGE_B;
        const uint32_t sB = sA + 2 * TILE_B;

        #pragma unroll
        for (int ks = 0; ks < 2; ks++) {
            uint32_t ah[4][4], al[4][4], bh[4][2], bl[4][2];
            #pragma unroll
            for (int mf = 0; mf < 4; mf++) {
                uint32_t ra = (wm * 64 + mf * 16) * ROWB + a_lane + ks * 32;
                ldsm4(ah[mf], sA + ra);
                ldsm4(al[mf], sA + TILE_B + ra);
            }
            #pragma unroll
            for (int p = 0; p < 2; p++) {
                uint32_t rb = (wn * 32 + p * 16) * ROWB + b_lane + ks * 32;
                uint32_t tmp[4];
                ldsm4(tmp, sB + rb);
                bh[2 * p][0] = tmp[0]; bh[2 * p][1] = tmp[1];
                bh[2 * p + 1][0] = tmp[2]; bh[2 * p + 1][1] = tmp[3];
                ldsm4(tmp, sB + TILE_B + rb);
                bl[2 * p][0] = tmp[0]; bl[2 * p][1] = tmp[1];
                bl[2 * p + 1][0] = tmp[2]; bl[2 * p + 1][1] = tmp[3];
            }
            #pragma unroll
            for (int mf = 0; mf < 4; mf++)
                #pragma unroll
                for (int nf = 0; nf < 4; nf++) {
                    mma16816(acc[mf][nf], ah[mf], bh[nf]);
                    mma16816(acc[mf][nf], ah[mf], bl[nf]);
                    mma16816(acc[mf][nf], al[mf], bh[nf]);
                }
        }
        __syncthreads();
        if (kc + NSTAGE < NCHUNK) fill(st, kc + NSTAGE);
    }

    // epilogue: y4[c][b][o]
    const int c     = ny >> 2;
    const int obase = (ny & 3) * 128;
    float* base = g_y4 + (size_t)c * (BATCH * OUTF);
    #pragma unroll
    for (int mf = 0; mf < 4; mf++) {
        int row = mx * 128 + wm * 64 + mf * 16 + g;
        #pragma unroll
        for (int nf = 0; nf < 4; nf++) {
            int col = obase + wn * 32 + nf * 8 + 2 * t;
            *(float2*)(base + (size_t)row * OUTF + col) =
                make_float2(acc[mf][nf][0], acc[mf][nf][1]);
            *(float2*)(base + (size_t)(row + 8) * OUTF + col) =
                make_float2(acc[mf][nf][2], acc[mf][nf][3]);
        }
    }
}

// ---------------- 3) reduce ----------------------------------------------------
__global__ void reduce_kernel(const float* __restrict__ phase,
                              const float* __restrict__ biases,
                              float* __restrict__ out) {
    int idx = blockIdx.x * blockDim.x + threadIdx.x;  // float4 index
    int b  = idx >> 7;
    int o4 = idx & 127;

    const float PI = 3.14159265358979323846f;
    float p = __ldg(phase + b);
    float tt = (p < 1.5f * PI) ? (p / (1.5f * PI)) : ((p - 0.5f * PI) / (1.5f * PI));
    float t2 = tt * tt, t3 = t2 * tt;
    float cc[4];
    cc[0] = t3 - 0.5f * t2;
    cc[1] = 1.0f - 2.5f * t3;
    cc[2] = 0.5f * t2 + 2.0f * t3;
    cc[3] = -0.5f * t3;

    const float4* P4 = (const float4*)g_y4;
    const float4* B4 = (const float4*)biases;
    float4 r = make_float4(0.f, 0.f, 0.f, 0.f);
    #pragma unroll
    for (int c = 0; c < NCP; c++) {
        float4 pp = P4[c * (BATCH * OUTF / 4) + idx];
        float4 bb = B4[c * (OUTF / 4) + o4];
        r.x = fmaf(cc[c], pp.x + bb.x, r.x);
        r.y = fmaf(cc[c], pp.y + bb.y, r.y);
        r.z = fmaf(cc[c], pp.z + bb.z, r.z);
        r.w = fmaf(cc[c], pp.w + bb.w, r.w);
    }
    ((float4*)out)[idx] = r;
}

// ---------------- launch -------------------------------------------------------
extern "C" void kernel_launch(void* const* d_in, const int* in_sizes, int n_in,
                              void* d_out, int out_size) {
    const float* input   = (const float*)d_in[0];   // [1024,512]
    const float* phase   = (const float*)d_in[1];   // [1024]
    const float* weights = (const float*)d_in[2];   // [4,512,512]
    const float* biases  = (const float*)d_in[3];   // [4,512]
    float* out = (float*)d_out;                     // [1024,512]

    cudaFuncSetAttribute(gemm_kernel,
                         cudaFuncAttributeMaxDynamicSharedMemorySize, SMEM_DYN);

    convert_kernel<<<1536, 256>>>(input, weights);

    dim3 grid(BATCH / 128, NCAT / 128);             // (8,16) = 128 CTAs
    gemm_kernel<<<grid, 256, SMEM_DYN>>>(0);

    reduce_kernel<<<(BATCH * OUTF / 4) / 256, 256>>>(phase, biases, out);
}